// round 7
// baseline (speedup 1.0000x reference)
#include <cuda_runtime.h>
#include <cstdint>

#define BATCH 1024
#define NUM_CLS 58

// ---------------- device scratch (no allocations allowed) ----------------
__device__ unsigned g_pw1[9 * 4 * 128];   // packed w1 signs, layout [tap][word][oc]
__device__ unsigned g_pw2[9 * 4 * 128];
__device__ unsigned g_pw3[9 * 4 * 128];
__device__ unsigned g_pw4[4 * 128];       // layout [word][oc]

// ---------------- weight sign packing (warp-ballot, coalesced) ----------------
__global__ void pack_weights_kernel(const float* __restrict__ w1, const float* __restrict__ w2,
                                    const float* __restrict__ w3, const float* __restrict__ w4) {
    int gw   = (blockIdx.x * blockDim.x + threadIdx.x) >> 5;
    int lane = threadIdx.x & 31;
    if (gw >= 2048) return;
    int t  = gw >> 9;
    int r  = gw & 511;
    int oc = r >> 2;
    int wi = r & 3;
    if (t < 3) {
        const float* w = (t == 0) ? w1 : ((t == 1) ? w2 : w3);
        unsigned* pw   = (t == 0) ? g_pw1 : ((t == 1) ? g_pw2 : g_pw3);
        const float* p = w + ((size_t)(oc * 128 + wi * 32 + lane)) * 9;
        float v[9];
#pragma unroll
        for (int k = 0; k < 9; k++) v[k] = p[k];
        unsigned myword = 0;
#pragma unroll
        for (int tap = 0; tap < 9; tap++) {
            unsigned wd = __ballot_sync(0xffffffffu, v[tap] >= 0.0f);
            if (lane == tap) myword = wd;
        }
        if (lane < 9) pw[(lane * 4 + wi) * 128 + oc] = myword;
    } else {
        float v = w4[oc * 128 + wi * 32 + lane];
        unsigned wd = __ballot_sync(0xffffffffu, v >= 0.0f);
        if (lane == 0) g_pw4[wi * 128 + oc] = wd;
    }
}

// ---------------- single merged model kernel: block = image, 128 threads (4 warps) ----------------
// Target 9 blocks/SM (regs <= 56): streaming-row conv keeps the live set small.
// Phase 0: fp32 conv0 (3->128, 3x3) + maxpool2x2 + sign -> packed a1s (15x15x4w) in smem
// Phase 1: binconv1 (3x3) + pool2x2 -> a2v (6x6) in smem
// Phase 2: binconv2 (3x3) + pool k2 s1 -> a3v (3x3) in smem
// Phase 3: binconv3 (3x3->1x1) + binconv4 (1x1) + relu + fp32 1x1 + softmax
__global__ __launch_bounds__(128, 9) void model_kernel(const float* __restrict__ x,
                                                       const float* __restrict__ w0,
                                                       const float* __restrict__ w5,
                                                       float* __restrict__ out) {
    __shared__ float xs[3 * 32 * 32];
    __shared__ uint4 a1s[225];
    __shared__ uint4 a2v[36];
    __shared__ uint4 a3v[9];
    __shared__ unsigned s4w[4];
    __shared__ float rs[128];
    __shared__ float lg[NUM_CLS];

    int b    = blockIdx.x;
    int tid  = threadIdx.x;
    int warp = tid >> 5;
    int lane = tid & 31;

    // ---- load image ----
    const float4* xb4 = (const float4*)(x + (size_t)b * 3072);
    float4* xs4 = (float4*)xs;
    for (int i = tid; i < 768; i += 128) xs4[i] = xb4[i];
    __syncthreads();

    // ---- phase 0: conv0 + pool + sign + pack (4 warps: cg = warp) ----
    // Streaming rows: row dy feeds cy=0 candidates via tap ky=dy (dy<=2) and
    // cy=1 candidates via tap ky=dy-1 (dy>=1). Per-accumulator order stays (c,ky,kx).
    {
        int cg = warp;
        int oc = cg * 32 + lane;

        float wr[27];
#pragma unroll
        for (int k = 0; k < 27; k++) wr[k] = w0[oc * 27 + k];

        for (int py = 0; py < 15; py++) {
            int y0 = 2 * py;
            for (int pxp = 0; pxp < 15; pxp += 2) {
                int x0 = 2 * pxp;            // multiple of 4 -> float4 aligned
                bool pair = (pxp + 1) < 15;

                float a0 = 0.f, a1 = 0.f, a2 = 0.f, a3 = 0.f;   // pixel pxp: (cy,cx) 00,01,10,11
                float a4 = 0.f, a5 = 0.f, a6 = 0.f, a7 = 0.f;   // pixel pxp+1
#pragma unroll
                for (int c = 0; c < 3; c++) {
#pragma unroll
                    for (int dy = 0; dy < 4; dy++) {
                        const float* row = &xs[c * 1024 + (y0 + dy) * 32 + x0];
                        float4 q = *(const float4*)row;
                        float e0 = q.x, e1 = q.y, e2 = q.z, e3 = q.w, e4, e5;
                        if (pair) {
                            float2 t = *(const float2*)(row + 4);
                            e4 = t.x; e5 = t.y;
                        } else { e4 = 0.f; e5 = 0.f; }
                        float ee[6] = {e0, e1, e2, e3, e4, e5};
                        if (dy <= 2) {
#pragma unroll
                            for (int kx = 0; kx < 3; kx++) {
                                float w = wr[c * 9 + dy * 3 + kx];
                                a0 += ee[0 + kx] * w;
                                a1 += ee[1 + kx] * w;
                                a4 += ee[2 + kx] * w;
                                a5 += ee[3 + kx] * w;
                            }
                        }
                        if (dy >= 1) {
#pragma unroll
                            for (int kx = 0; kx < 3; kx++) {
                                float w = wr[c * 9 + (dy - 1) * 3 + kx];
                                a2 += ee[0 + kx] * w;
                                a3 += ee[1 + kx] * w;
                                a6 += ee[2 + kx] * w;
                                a7 += ee[3 + kx] * w;
                            }
                        }
                    }
                }
                float best0 = fmaxf(fmaxf(a0, a1), fmaxf(a2, a3));
                float best1 = fmaxf(fmaxf(a4, a5), fmaxf(a6, a7));

                int p = py * 15 + pxp;
                unsigned word0 = __ballot_sync(0xffffffffu, best0 >= 0.0f);
                unsigned word1 = __ballot_sync(0xffffffffu, best1 >= 0.0f);
                if (lane == 0) {
                    ((unsigned*)a1s)[p * 4 + cg] = word0;
                    if (pair) ((unsigned*)a1s)[(p + 1) * 4 + cg] = word1;
                }
            }
        }
    }
    __syncthreads();

    // ---- phase 1: binconv1 (4 warps: cg = warp, 36 pixels each) ----
    {
        int cg = warp;
        int oc = cg * 32 + lane;

        uint4 wr[9];
#pragma unroll
        for (int tap = 0; tap < 9; tap++) {
            wr[tap].x = g_pw1[(tap * 4 + 0) * 128 + oc];
            wr[tap].y = g_pw1[(tap * 4 + 1) * 128 + oc];
            wr[tap].z = g_pw1[(tap * 4 + 2) * 128 + oc];
            wr[tap].w = g_pw1[(tap * 4 + 3) * 128 + oc];
        }

        for (int p = 0; p < 36; p++) {
            int py = p / 6, px = p - py * 6;
            int y0 = 2 * py, x0 = 2 * px;

            int smin = 1 << 30;
#pragma unroll
            for (int cy = 0; cy < 2; cy++)
#pragma unroll
                for (int cx = 0; cx < 2; cx++) {
                    int s = 0;
#pragma unroll
                    for (int ky = 0; ky < 3; ky++)
#pragma unroll
                        for (int kx = 0; kx < 3; kx++) {
                            uint4 xv = a1s[(y0 + cy + ky) * 15 + (x0 + cx + kx)];
                            uint4 wv = wr[ky * 3 + kx];
                            s += __popc(xv.x ^ wv.x) + __popc(xv.y ^ wv.y) +
                                 __popc(xv.z ^ wv.z) + __popc(xv.w ^ wv.w);
                        }
                    smin = min(smin, s);
                }
            // dot = 1152 - 2*smin ; sign bit = (dot >= 0)
            unsigned word = __ballot_sync(0xffffffffu, smin <= 576);
            if (lane == 0) ((unsigned*)a2v)[p * 4 + cg] = word;
        }
    }
    __syncthreads();

    // ---- phase 2: binconv2 (4 warps: cg = warp, 9 pixels each) ----
    {
        int cg = warp;
        int oc = cg * 32 + lane;

        uint4 wr[9];
#pragma unroll
        for (int tap = 0; tap < 9; tap++) {
            wr[tap].x = g_pw2[(tap * 4 + 0) * 128 + oc];
            wr[tap].y = g_pw2[(tap * 4 + 1) * 128 + oc];
            wr[tap].z = g_pw2[(tap * 4 + 2) * 128 + oc];
            wr[tap].w = g_pw2[(tap * 4 + 3) * 128 + oc];
        }

        for (int p = 0; p < 9; p++) {
            int py = p / 3, px = p - py * 3;

            int smin = 1 << 30;
#pragma unroll
            for (int cy = 0; cy < 2; cy++)
#pragma unroll
                for (int cx = 0; cx < 2; cx++) {
                    int s = 0;
#pragma unroll
                    for (int ky = 0; ky < 3; ky++)
#pragma unroll
                        for (int kx = 0; kx < 3; kx++) {
                            uint4 xv = a2v[(py + cy + ky) * 6 + (px + cx + kx)];
                            uint4 wv = wr[ky * 3 + kx];
                            s += __popc(xv.x ^ wv.x) + __popc(xv.y ^ wv.y) +
                                 __popc(xv.z ^ wv.z) + __popc(xv.w ^ wv.w);
                        }
                    smin = min(smin, s);
                }
            unsigned word = __ballot_sync(0xffffffffu, smin <= 576);
            if (lane == 0) ((unsigned*)a3v)[p * 4 + cg] = word;
        }
    }
    __syncthreads();

    // ---- phase 3: head (128 threads = output channel) ----
    {
        int oc = tid;
        int s = 0;
#pragma unroll
        for (int tap = 0; tap < 9; tap++) {
            uint4 xv = a3v[tap];
            s += __popc(xv.x ^ g_pw3[(tap * 4 + 0) * 128 + oc]);
            s += __popc(xv.y ^ g_pw3[(tap * 4 + 1) * 128 + oc]);
            s += __popc(xv.z ^ g_pw3[(tap * 4 + 2) * 128 + oc]);
            s += __popc(xv.w ^ g_pw3[(tap * 4 + 3) * 128 + oc]);
        }
        unsigned word = __ballot_sync(0xffffffffu, s <= 576);  // sign(1152 - 2s)
        if (lane == 0) s4w[warp] = word;
    }
    __syncthreads();

    {
        int oc = tid;
        int t = 0;
#pragma unroll
        for (int wi = 0; wi < 4; wi++) t += __popc(s4w[wi] ^ g_pw4[wi * 128 + oc]);
        rs[oc] = fmaxf((float)(128 - 2 * t), 0.0f);
    }
    __syncthreads();

    // fp32 1x1 conv to NUM_CLS logits
    if (tid < NUM_CLS) {
        float acc = 0.0f;
#pragma unroll 8
        for (int o = 0; o < 128; o++) acc += w5[tid * 128 + o] * rs[o];
        lg[tid] = acc;
    }
    __syncthreads();

    // softmax over NUM_CLS
    if (tid < NUM_CLS) {
        float m = -3.4e38f;
        for (int j = 0; j < NUM_CLS; j++) m = fmaxf(m, lg[j]);
        float den = 0.0f;
        for (int j = 0; j < NUM_CLS; j++) den += expf(lg[j] - m);
        out[(size_t)b * NUM_CLS + tid] = expf(lg[tid] - m) / den;
    }
}

// ---------------- launch ----------------
extern "C" void kernel_launch(void* const* d_in, const int* in_sizes, int n_in,
                              void* d_out, int out_size) {
    const float* x  = (const float*)d_in[0];
    const float* w0 = (const float*)d_in[1];
    const float* w1 = (const float*)d_in[2];
    const float* w2 = (const float*)d_in[3];
    const float* w3 = (const float*)d_in[4];
    const float* w4 = (const float*)d_in[5];
    const float* w5 = (const float*)d_in[6];
    float* out = (float*)d_out;

    pack_weights_kernel<<<256, 256>>>(w1, w2, w3, w4);
    model_kernel<<<BATCH, 128>>>(x, w0, w5, out);
}

// round 8
// speedup vs baseline: 1.0278x; 1.0278x over previous
#include <cuda_runtime.h>
#include <cstdint>

#define BATCH 1024
#define NUM_CLS 58

// ---------------- device scratch (no allocations allowed) ----------------
__device__ unsigned g_pw1[9 * 4 * 128];   // packed w1 signs, layout [tap][word][oc]
__device__ unsigned g_pw2[9 * 4 * 128];
__device__ unsigned g_pw3[9 * 4 * 128];
__device__ unsigned g_pw4[4 * 128];       // layout [word][oc]

// ---------------- weight sign packing (warp-ballot, coalesced) ----------------
__global__ void pack_weights_kernel(const float* __restrict__ w1, const float* __restrict__ w2,
                                    const float* __restrict__ w3, const float* __restrict__ w4) {
    int gw   = (blockIdx.x * blockDim.x + threadIdx.x) >> 5;
    int lane = threadIdx.x & 31;
    if (gw >= 2048) return;
    int t  = gw >> 9;
    int r  = gw & 511;
    int oc = r >> 2;
    int wi = r & 3;
    if (t < 3) {
        const float* w = (t == 0) ? w1 : ((t == 1) ? w2 : w3);
        unsigned* pw   = (t == 0) ? g_pw1 : ((t == 1) ? g_pw2 : g_pw3);
        const float* p = w + ((size_t)(oc * 128 + wi * 32 + lane)) * 9;
        float v[9];
#pragma unroll
        for (int k = 0; k < 9; k++) v[k] = p[k];
        unsigned myword = 0;
#pragma unroll
        for (int tap = 0; tap < 9; tap++) {
            unsigned wd = __ballot_sync(0xffffffffu, v[tap] >= 0.0f);
            if (lane == tap) myword = wd;
        }
        if (lane < 9) pw[(lane * 4 + wi) * 128 + oc] = myword;
    } else {
        float v = w4[oc * 128 + wi * 32 + lane];
        unsigned wd = __ballot_sync(0xffffffffu, v >= 0.0f);
        if (lane == 0) g_pw4[wi * 128 + oc] = wd;
    }
}

// ---- phase-0 helper: PIX pooled pixels sharing 12-col row loads ----
// Per-candidate accumulation order is (c asc, ky asc, kx asc) — identical to prior rounds.
template<int PIX>
__device__ __forceinline__ void conv_group(const float* __restrict__ xs, int y0, int x0c,
                                           const float* __restrict__ wr, int cg,
                                           unsigned* __restrict__ a1w, int pbase, int lane,
                                           size_t bofs) {
    constexpr int NW = (PIX == 4) ? 3 : 2;    // float4 loads per row
    float acc[PIX][4];
#pragma unroll
    for (int pi = 0; pi < PIX; pi++) {
        acc[pi][0] = 0.f; acc[pi][1] = 0.f; acc[pi][2] = 0.f; acc[pi][3] = 0.f;
    }
#pragma unroll
    for (int c = 0; c < 3; c++) {
#pragma unroll
        for (int dy = 0; dy < 4; dy++) {
            float e[NW * 4];
            const float4* r4 = (const float4*)&xs[c * 1024 + (y0 + dy) * 32 + x0c];
#pragma unroll
            for (int j = 0; j < NW; j++) {
                float4 q = r4[j];
                e[j * 4 + 0] = q.x; e[j * 4 + 1] = q.y; e[j * 4 + 2] = q.z; e[j * 4 + 3] = q.w;
            }
#pragma unroll
            for (int kx = 0; kx < 3; kx++) {
                if (dy <= 2) {
                    float w = wr[c * 9 + dy * 3 + kx];
#pragma unroll
                    for (int pi = 0; pi < PIX; pi++) {
                        acc[pi][0] += e[2 * pi + kx] * w;
                        acc[pi][1] += e[2 * pi + 1 + kx] * w;
                    }
                }
                if (dy >= 1) {
                    float w = wr[c * 9 + (dy - 1) * 3 + kx];
#pragma unroll
                    for (int pi = 0; pi < PIX; pi++) {
                        acc[pi][2] += e[2 * pi + kx] * w;
                        acc[pi][3] += e[2 * pi + 1 + kx] * w;
                    }
                }
            }
        }
    }
#pragma unroll
    for (int pi = 0; pi < PIX; pi++) {
        float best = fmaxf(fmaxf(acc[pi][0], acc[pi][1]), fmaxf(acc[pi][2], acc[pi][3]));
        unsigned word = __ballot_sync(0xffffffffu, best >= 0.0f);
        if (lane == 0) a1w[bofs + (size_t)(pbase + pi) * 4 + cg] = word;
    }
}

// ---------------- single merged model kernel: block = image, 128 threads (4 warps) ----------------
__global__ __launch_bounds__(128, 7) void model_kernel(const float* __restrict__ x,
                                                       const float* __restrict__ w0,
                                                       const float* __restrict__ w5,
                                                       float* __restrict__ out) {
    __shared__ float xs[3 * 32 * 32];
    __shared__ uint4 a1s[225];
    __shared__ uint4 a2v[36];
    __shared__ uint4 a3v[9];
    __shared__ unsigned s4w[4];
    __shared__ float rs[128];
    __shared__ float lg[NUM_CLS];

    int b    = blockIdx.x;
    int tid  = threadIdx.x;
    int warp = tid >> 5;
    int lane = tid & 31;

    // ---- load image ----
    const float4* xb4 = (const float4*)(x + (size_t)b * 3072);
    float4* xs4 = (float4*)xs;
    for (int i = tid; i < 768; i += 128) xs4[i] = xb4[i];
    __syncthreads();

    // ---- phase 0: conv0 + pool + sign + pack (4 warps: cg = warp) ----
    {
        int cg = warp;
        int oc = cg * 32 + lane;

        float wr[27];
#pragma unroll
        for (int k = 0; k < 27; k++) wr[k] = w0[oc * 27 + k];

        unsigned* a1w = (unsigned*)a1s;
        for (int py = 0; py < 15; py++) {
            int y0 = 2 * py;
            int pb = py * 15;
            // groups of pooled pixels: {0-3}, {4-7}, {8-11}, {12-14}
            conv_group<4>(xs, y0, 0,  wr, cg, a1w, pb + 0,  lane, 0);
            conv_group<4>(xs, y0, 8,  wr, cg, a1w, pb + 4,  lane, 0);
            conv_group<4>(xs, y0, 16, wr, cg, a1w, pb + 8,  lane, 0);
            conv_group<3>(xs, y0, 24, wr, cg, a1w, pb + 12, lane, 0);
        }
    }
    __syncthreads();

    // ---- phase 1: binconv1 (4 warps: cg = warp, 36 pixels each) ----
    {
        int cg = warp;
        int oc = cg * 32 + lane;

        uint4 wr[9];
#pragma unroll
        for (int tap = 0; tap < 9; tap++) {
            wr[tap].x = g_pw1[(tap * 4 + 0) * 128 + oc];
            wr[tap].y = g_pw1[(tap * 4 + 1) * 128 + oc];
            wr[tap].z = g_pw1[(tap * 4 + 2) * 128 + oc];
            wr[tap].w = g_pw1[(tap * 4 + 3) * 128 + oc];
        }

        for (int p = 0; p < 36; p++) {
            int py = p / 6, px = p - py * 6;
            int y0 = 2 * py, x0 = 2 * px;

            int smin = 1 << 30;
#pragma unroll
            for (int cy = 0; cy < 2; cy++)
#pragma unroll
                for (int cx = 0; cx < 2; cx++) {
                    int s = 0;
#pragma unroll
                    for (int ky = 0; ky < 3; ky++)
#pragma unroll
                        for (int kx = 0; kx < 3; kx++) {
                            uint4 xv = a1s[(y0 + cy + ky) * 15 + (x0 + cx + kx)];
                            uint4 wv = wr[ky * 3 + kx];
                            s += __popc(xv.x ^ wv.x) + __popc(xv.y ^ wv.y) +
                                 __popc(xv.z ^ wv.z) + __popc(xv.w ^ wv.w);
                        }
                    smin = min(smin, s);
                }
            // dot = 1152 - 2*smin ; sign bit = (dot >= 0)
            unsigned word = __ballot_sync(0xffffffffu, smin <= 576);
            if (lane == 0) ((unsigned*)a2v)[p * 4 + cg] = word;
        }
    }
    __syncthreads();

    // ---- phase 2: binconv2 (4 warps: cg = warp, 9 pixels each) ----
    {
        int cg = warp;
        int oc = cg * 32 + lane;

        uint4 wr[9];
#pragma unroll
        for (int tap = 0; tap < 9; tap++) {
            wr[tap].x = g_pw2[(tap * 4 + 0) * 128 + oc];
            wr[tap].y = g_pw2[(tap * 4 + 1) * 128 + oc];
            wr[tap].z = g_pw2[(tap * 4 + 2) * 128 + oc];
            wr[tap].w = g_pw2[(tap * 4 + 3) * 128 + oc];
        }

        for (int p = 0; p < 9; p++) {
            int py = p / 3, px = p - py * 3;

            int smin = 1 << 30;
#pragma unroll
            for (int cy = 0; cy < 2; cy++)
#pragma unroll
                for (int cx = 0; cx < 2; cx++) {
                    int s = 0;
#pragma unroll
                    for (int ky = 0; ky < 3; ky++)
#pragma unroll
                        for (int kx = 0; kx < 3; kx++) {
                            uint4 xv = a2v[(py + cy + ky) * 6 + (px + cx + kx)];
                            uint4 wv = wr[ky * 3 + kx];
                            s += __popc(xv.x ^ wv.x) + __popc(xv.y ^ wv.y) +
                                 __popc(xv.z ^ wv.z) + __popc(xv.w ^ wv.w);
                        }
                    smin = min(smin, s);
                }
            unsigned word = __ballot_sync(0xffffffffu, smin <= 576);
            if (lane == 0) ((unsigned*)a3v)[p * 4 + cg] = word;
        }
    }
    __syncthreads();

    // ---- phase 3: head (128 threads = output channel) ----
    {
        int oc = tid;
        int s = 0;
#pragma unroll
        for (int tap = 0; tap < 9; tap++) {
            uint4 xv = a3v[tap];
            s += __popc(xv.x ^ g_pw3[(tap * 4 + 0) * 128 + oc]);
            s += __popc(xv.y ^ g_pw3[(tap * 4 + 1) * 128 + oc]);
            s += __popc(xv.z ^ g_pw3[(tap * 4 + 2) * 128 + oc]);
            s += __popc(xv.w ^ g_pw3[(tap * 4 + 3) * 128 + oc]);
        }
        unsigned word = __ballot_sync(0xffffffffu, s <= 576);  // sign(1152 - 2s)
        if (lane == 0) s4w[warp] = word;
    }
    __syncthreads();

    {
        int oc = tid;
        int t = 0;
#pragma unroll
        for (int wi = 0; wi < 4; wi++) t += __popc(s4w[wi] ^ g_pw4[wi * 128 + oc]);
        rs[oc] = fmaxf((float)(128 - 2 * t), 0.0f);
    }
    __syncthreads();

    // fp32 1x1 conv to NUM_CLS logits
    if (tid < NUM_CLS) {
        float acc = 0.0f;
#pragma unroll 8
        for (int o = 0; o < 128; o++) acc += w5[tid * 128 + o] * rs[o];
        lg[tid] = acc;
    }
    __syncthreads();

    // softmax over NUM_CLS
    if (tid < NUM_CLS) {
        float m = -3.4e38f;
        for (int j = 0; j < NUM_CLS; j++) m = fmaxf(m, lg[j]);
        float den = 0.0f;
        for (int j = 0; j < NUM_CLS; j++) den += expf(lg[j] - m);
        out[(size_t)b * NUM_CLS + tid] = expf(lg[tid] - m) / den;
    }
}

// ---------------- launch ----------------
extern "C" void kernel_launch(void* const* d_in, const int* in_sizes, int n_in,
                              void* d_out, int out_size) {
    const float* x  = (const float*)d_in[0];
    const float* w0 = (const float*)d_in[1];
    const float* w1 = (const float*)d_in[2];
    const float* w2 = (const float*)d_in[3];
    const float* w3 = (const float*)d_in[4];
    const float* w4 = (const float*)d_in[5];
    const float* w5 = (const float*)d_in[6];
    float* out = (float*)d_out;

    pack_weights_kernel<<<256, 256>>>(w1, w2, w3, w4);
    model_kernel<<<BATCH, 128>>>(x, w0, w5, out);
}